// round 12
// baseline (speedup 1.0000x reference)
#include <cuda_runtime.h>
#include <math.h>

#define BB 64
#define PP 24564
#define CC 81
#define TT 24
#define THRESH_F 0.5f
#define FULLMASK 0xffffffffu

// fused kernel geometry
#define NCONF 592                      // persistent conf blocks (4/SM)
#define NMATCH 148                     // match blocks (1/SM)
#define CW_WARPS 2
#define CW_BUFS 2
#define CW_ROWS 32
#define CW_F4 ((CW_ROWS * CC) / 4)     // 648 float4 per tile
#define CW_TILEF (CW_ROWS * CC)        // 2592 floats
#define CONF_TILES ((BB * PP) / CW_ROWS)      // 49128
#define CONF_WSTRIDE (NCONF * CW_WARPS)       // 1184
#define FUSED_SMEM (CW_WARPS * CW_BUFS * CW_TILEF * 4)  // 41472 B

#define MCH_PER_B 768                  // 32-prior chunks per batch (ceil 24564/32)
#define MCHUNKS (MCH_PER_B * BB)       // 49152
#define MWARPS (NMATCH * 2)            // 296

// ---------------------------------------------------------------------------
// Scratch (device globals — no allocation allowed)
// ---------------------------------------------------------------------------
__device__ unsigned long long g_bp[BB * TT];        // packed (iou_bits<<32)|~p
__device__ unsigned char g_match[(size_t)BB * PP];  // 0xFF = bestov<=0.5, else bt
__device__ float g_closs[(size_t)BB * PP];          // lse - c0 (raw), positives zeroed later
__device__ unsigned int g_plist[(size_t)BB * PP];   // packed (row<<8)|lbl
__device__ int g_pcount;
__device__ double g_loc, g_poscls, g_negcls;
__device__ int g_numpos[BB];
__device__ int g_nsel;

__device__ __forceinline__ void cp_async16(unsigned int smem_dst, const void* gsrc) {
    asm volatile("cp.async.cg.shared.global [%0], [%1], 16;"
                 :: "r"(smem_dst), "l"(gsrc));
}

// ---------------------------------------------------------------------------
// Kernel 0: zero-init scratch
// ---------------------------------------------------------------------------
__global__ void k_init() {
    int i = blockIdx.x * blockDim.x + threadIdx.x;
    if (i < BB * TT) g_bp[i] = 0ULL;
    if (i < BB) g_numpos[i] = 0;
    if (i == 0) { g_loc = 0.0; g_poscls = 0.0; g_negcls = 0.0; g_nsel = 0; g_pcount = 0; }
}

// ---------------------------------------------------------------------------
// Kernel 1 (FUSED): conf streaming + matching run CONCURRENTLY.
//   blocks [0, NCONF): persistent cp.async double-buffered conf pass
//     (memory-bound, ~4 TB/s wall, issue slots mostly idle)
//   blocks [NCONF, NCONF+NMATCH): matching (compute-bound, hides under conf)
// conf no longer depends on matching: it writes closs_raw = lse - c0 for ALL
// rows; positives are recorded in g_plist and fixed up by k_zero afterwards.
// ---------------------------------------------------------------------------
__global__ void __launch_bounds__(64) k_fused(const float* __restrict__ conf_pred,
                                              const float* __restrict__ loc_pred,
                                              const float* __restrict__ targets,
                                              const float* __restrict__ anchors) {
    extern __shared__ float smem[];
    const int lane = threadIdx.x & 31;
    const int w = threadIdx.x >> 5;

    if (blockIdx.x < NCONF) {
        // ================= CONF PATH (R10 design, best measured) =============
        const int gw = blockIdx.x * CW_WARPS + w;
        float* wbase = smem + w * (CW_BUFS * CW_TILEF);
        unsigned int sb0 = (unsigned int)__cvta_generic_to_shared(wbase);

        int tile = gw;
        if (tile >= CONF_TILES) return;
        {
            const float4* src = (const float4*)(conf_pred + (size_t)tile * CW_TILEF);
            #pragma unroll
            for (int i = lane; i < CW_F4; i += 32)
                cp_async16(sb0 + i * 16, src + i);
            asm volatile("cp.async.commit_group;");
        }
        int buf = 0;
        for (; tile < CONF_TILES; tile += CONF_WSTRIDE) {
            const int nt = tile + CONF_WSTRIDE;
            if (nt < CONF_TILES) {
                const float4* src = (const float4*)(conf_pred + (size_t)nt * CW_TILEF);
                unsigned int dst = sb0 + (buf ^ 1) * (CW_TILEF * 4);
                #pragma unroll
                for (int i = lane; i < CW_F4; i += 32)
                    cp_async16(dst + i * 16, src + i);
            }
            asm volatile("cp.async.commit_group;");
            asm volatile("cp.async.wait_group 1;");
            __syncwarp();

            const float* rp = wbase + buf * CW_TILEF + lane * CC;
            float a0 = 0.f, a1 = 0.f, a2 = 0.f;
            #pragma unroll 9
            for (int e = 0; e < CC; e += 3) {
                a0 += __expf(rp[e]);
                a1 += __expf(rp[e + 1]);
                a2 += __expf(rp[e + 2]);
            }
            const float lse = __logf((a0 + a1) + a2);
            g_closs[(size_t)tile * CW_ROWS + lane] = lse - rp[0];   // raw for ALL rows

            buf ^= 1;
            __syncwarp();
        }
    } else {
        // ================= MATCH PATH =========================================
        // warp-owned contiguous chunk ranges; truth cache in this warp's smem
        // region; per-truth running warp max cached in 24 registers (iou bits
        // only — within a warp p ascends, so equal-bits skip keeps min-p).
        const int gw2 = (blockIdx.x - NCONF) * 2 + w;     // 0..295
        float* tc = smem + w * (CW_BUFS * CW_TILEF);      // reuse conf smem region
        float* t_box = tc;            // [24][4] xyxy
        float* t_ta  = tc + 96;       // [24]
        float* t_cwh = tc + 120;      // [24][4]
        float* t_lbl = tc + 216;      // [24]

        const int c0 = (int)(((long long)gw2 * MCHUNKS) / MWARPS);
        const int c1 = (int)(((long long)(gw2 + 1) * MCHUNKS) / MWARPS);

        unsigned int cur[TT];
        int bcur = -1;

        for (int c = c0; c < c1; c++) {
            const int b = c / MCH_PER_B;
            const int p = (c - b * MCH_PER_B) * 32 + lane;
            if (b != bcur) {
                __syncwarp();
                if (lane < TT) {
                    const float* tr = targets + ((size_t)b * TT + lane) * 5;
                    float x0 = tr[0], y0 = tr[1], x1 = tr[2], y1 = tr[3];
                    t_box[lane * 4 + 0] = x0; t_box[lane * 4 + 1] = y0;
                    t_box[lane * 4 + 2] = x1; t_box[lane * 4 + 3] = y1;
                    t_ta[lane] = (x1 - x0) * (y1 - y0);
                    t_cwh[lane * 4 + 0] = (x0 + x1) * 0.5f;
                    t_cwh[lane * 4 + 1] = (y0 + y1) * 0.5f;
                    t_cwh[lane * 4 + 2] = x1 - x0;
                    t_cwh[lane * 4 + 3] = y1 - y0;
                    t_lbl[lane] = tr[4];
                }
                __syncwarp();
                #pragma unroll
                for (int t = 0; t < TT; t++) cur[t] = 0u;
                bcur = b;
            }

            const bool valid = (p < PP);
            float4 a = make_float4(0.f, 0.f, 1.f, 1.f);
            if (valid) a = ((const float4*)anchors)[p];
            const float ax0 = a.x - a.z * 0.5f, ay0 = a.y - a.w * 0.5f;
            const float ax1 = a.x + a.z * 0.5f, ay1 = a.y + a.w * 0.5f;
            const float aarea = (ax1 - ax0) * (ay1 - ay0);

            float best = -1.0f; int bt = 0;
            #pragma unroll
            for (int t = 0; t < TT; t++) {
                float lx = fmaxf(t_box[t * 4 + 0], ax0), ly = fmaxf(t_box[t * 4 + 1], ay0);
                float rx = fminf(t_box[t * 4 + 2], ax1), ry = fminf(t_box[t * 4 + 3], ay1);
                float ww = fmaxf(rx - lx, 0.f), hh = fmaxf(ry - ly, 0.f);
                float inter = ww * hh;
                float iou = __fdividef(inter, t_ta[t] + aarea - inter);
                if (iou > best) { best = iou; bt = t; }   // strict >: first index
                unsigned int ib = valid ? __float_as_uint(iou) : 0u;
                if (__any_sync(FULLMASK, ib > cur[t])) {
                    unsigned long long pk = valid
                        ? (((unsigned long long)ib << 32)
                           | (unsigned long long)(unsigned int)(~p))
                        : 0ULL;
                    #pragma unroll
                    for (int o = 16; o; o >>= 1) {
                        unsigned long long q = __shfl_xor_sync(FULLMASK, pk, o);
                        if (q > pk) pk = q;
                    }
                    cur[t] = (unsigned int)(pk >> 32);
                    if (lane == 0) atomicMax(&g_bp[b * TT + t], pk);
                }
            }

            const bool pos = valid && (best > THRESH_F);
            const unsigned int pm = __ballot_sync(FULLMASK, pos);
            const unsigned int row = (unsigned int)(b * PP + p);
            float lt = 0.f; int lbl = 0;
            if (pos) {
                lbl = (int)t_lbl[bt];
                float4 lp = ((const float4*)loc_pred)[row];
                float e0 = (t_cwh[bt * 4 + 0] - a.x) / a.z;
                float e1 = (t_cwh[bt * 4 + 1] - a.y) / a.w;
                float e2 = __logf(t_cwh[bt * 4 + 2]) - __logf(a.z);
                float e3 = __logf(t_cwh[bt * 4 + 3]) - __logf(a.w);
                float d, ad;
                d = lp.x - e0; ad = fabsf(d); lt += (ad < 1.f) ? 0.5f * d * d : ad - 0.5f;
                d = lp.y - e1; ad = fabsf(d); lt += (ad < 1.f) ? 0.5f * d * d : ad - 0.5f;
                d = lp.z - e2; ad = fabsf(d); lt += (ad < 1.f) ? 0.5f * d * d : ad - 0.5f;
                d = lp.w - e3; ad = fabsf(d); lt += (ad < 1.f) ? 0.5f * d * d : ad - 0.5f;
            }
            if (pm) {   // warp-aggregated positive bookkeeping
                const int n = __popc(pm);
                const int leader = __ffs(pm) - 1;
                unsigned int base = 0;
                if (lane == leader) base = (unsigned int)atomicAdd(&g_pcount, n);
                base = __shfl_sync(FULLMASK, base, leader);
                if (pos) {
                    int off = __popc(pm & ((1u << lane) - 1u));
                    g_plist[base + off] = (row << 8) | (unsigned int)lbl;
                }
                double dlt = (double)lt;
                #pragma unroll
                for (int o = 16; o; o >>= 1) dlt += __shfl_xor_sync(FULLMASK, dlt, o);
                if (lane == leader) {
                    atomicAdd(&g_loc, dlt);
                    atomicAdd(&g_numpos[b], n);
                }
            }
            if (valid) g_match[row] = pos ? (unsigned char)bt : (unsigned char)0xFF;
        }
    }
}

// ---------------------------------------------------------------------------
// Kernel 2: scatter fixup — row p = best_prior[b][t] becomes positive with
// truth t (last t wins among duplicates) iff its best overlap <= 0.5.
// ---------------------------------------------------------------------------
__global__ void k_fix(const float* __restrict__ loc_pred,
                      const float* __restrict__ targets,
                      const float* __restrict__ anchors) {
    const int b = blockIdx.x;
    const int t = threadIdx.x;
    if (t >= TT) return;
    unsigned long long pk = g_bp[b * TT + t];
    const int p = (int)(~(unsigned int)(pk & 0xFFFFFFFFull));
    unsigned int peers = __match_any_sync(0x00FFFFFFu, p);
    if (t != 31 - __clz(peers)) return;          // last t wins
    const unsigned int row = (unsigned int)(b * PP + p);
    if (g_match[row] != 0xFF) return;            // bt-match already positive

    const float* tr = targets + ((size_t)b * TT + t) * 5;
    float x0 = tr[0], y0 = tr[1], x1 = tr[2], y1 = tr[3];
    int lbl = (int)tr[4];
    int idx = atomicAdd(&g_pcount, 1);
    g_plist[idx] = (row << 8) | (unsigned int)lbl;

    float4 a = ((const float4*)anchors)[p];
    float4 lp = ((const float4*)loc_pred)[row];
    float e0 = ((x0 + x1) * 0.5f - a.x) / a.z;
    float e1 = ((y0 + y1) * 0.5f - a.y) / a.w;
    float e2 = __logf(x1 - x0) - __logf(a.z);
    float e3 = __logf(y1 - y0) - __logf(a.w);
    float d, ad, lt = 0.f;
    d = lp.x - e0; ad = fabsf(d); lt += (ad < 1.f) ? 0.5f * d * d : ad - 0.5f;
    d = lp.y - e1; ad = fabsf(d); lt += (ad < 1.f) ? 0.5f * d * d : ad - 0.5f;
    d = lp.z - e2; ad = fabsf(d); lt += (ad < 1.f) ? 0.5f * d * d : ad - 0.5f;
    d = lp.w - e3; ad = fabsf(d); lt += (ad < 1.f) ? 0.5f * d * d : ad - 0.5f;
    atomicAdd(&g_loc, (double)lt);
    atomicAdd(&g_numpos[b], 1);
}

// ---------------------------------------------------------------------------
// Kernel 3: positive fixup. For each (row,lbl) in g_plist:
//   poscls += closs_raw[row] + conf[row][0] - conf[row][lbl]   (= lse - conf[lbl])
//   closs[row] = 0   (so hard-negative mining skips positives)
// ---------------------------------------------------------------------------
__global__ void k_zero(const float* __restrict__ conf_pred) {
    const int n = g_pcount;
    const int lane = threadIdx.x & 31;
    double acc = 0.0;
    for (int i = blockIdx.x * blockDim.x + threadIdx.x; i < n;
         i += gridDim.x * blockDim.x) {
        unsigned int e = g_plist[i];
        size_t row = (size_t)(e >> 8);
        int lbl = (int)(e & 255u);
        const float* cp = conf_pred + row * CC;
        acc += (double)(g_closs[row] + cp[0] - cp[lbl]);
        g_closs[row] = 0.f;
    }
    #pragma unroll
    for (int o = 16; o; o >>= 1) acc += __shfl_xor_sync(FULLMASK, acc, o);
    if (lane == 0 && acc != 0.0) atomicAdd(&g_poscls, acc);
}

// ---------------------------------------------------------------------------
// Kernel 4: per-batch exact K-th-largest; register-cached values, warp-
// aggregated histogram atomics (closs clusters into few bins).
// ---------------------------------------------------------------------------
__global__ void __launch_bounds__(1024) k_select() {
    __shared__ int hist[256];
    __shared__ unsigned int s_sel;
    __shared__ int s_r;
    __shared__ double s_sum;
    __shared__ int s_cnt;

    const int b = blockIdx.x;
    const int tid = threadIdx.x;
    const int lane = tid & 31;
    const int np = g_numpos[b];
    long long Kl = 3LL * np;
    if (Kl > PP - 1) Kl = PP - 1;
    const int K = (int)Kl;
    if (K <= 0) {
        if (tid == 0) atomicAdd(&g_nsel, np);
        return;
    }
    const float* cl = g_closs + (size_t)b * PP;

    // Padding 0u (=0.0f) lands in bin 0; selection never descends there
    // (K-th largest closs > 0).
    unsigned int v[24];
    #pragma unroll
    for (int i = 0; i < 24; i++) {
        int idx = tid + i * 1024;
        v[i] = (idx < PP) ? __float_as_uint(cl[idx]) : 0u;
    }

    unsigned int prefix = 0, pmask = 0;
    int r = K;
    #pragma unroll
    for (int shift = 24; shift >= 0; shift -= 8) {
        if (tid < 256) hist[tid] = 0;
        __syncthreads();
        #pragma unroll
        for (int i = 0; i < 24; i++) {
            unsigned int u = v[i];
            bool act = ((u & pmask) == prefix);
            unsigned int bal = __ballot_sync(FULLMASK, act);
            if (act) {
                unsigned int bin = (u >> shift) & 255u;
                unsigned int peers = __match_any_sync(bal, bin);
                if (lane == __ffs(peers) - 1)
                    atomicAdd(&hist[bin], __popc(peers));
            }
        }
        __syncthreads();
        if (tid == 0) {
            int cum = 0; unsigned int sel = 0;
            for (int bin = 255; bin >= 0; bin--) {
                int nc = cum + hist[bin];
                if (nc >= r) { sel = (unsigned int)bin; break; }
                cum = nc;
            }
            s_sel = sel; s_r = r - cum;
        }
        __syncthreads();
        prefix |= s_sel << shift;
        pmask |= 0xFFu << shift;
        r = s_r;
    }
    const float theta = __uint_as_float(prefix);   // exact K-th largest

    if (tid == 0) { s_sum = 0.0; s_cnt = 0; }
    __syncthreads();
    double sum = 0.0; int cnt = 0;
    #pragma unroll
    for (int i = 0; i < 24; i++) {
        float f = __uint_as_float(v[i]);
        if (f > theta) { sum += (double)f; cnt++; }
    }
    #pragma unroll
    for (int o = 16; o; o >>= 1) {
        sum += __shfl_xor_sync(FULLMASK, sum, o);
        cnt += __shfl_xor_sync(FULLMASK, cnt, o);
    }
    if (lane == 0) { atomicAdd(&s_sum, sum); atomicAdd(&s_cnt, cnt); }
    __syncthreads();
    if (tid == 0) {
        double negsum = s_sum + (double)(K - s_cnt) * (double)theta;
        atomicAdd(&g_negcls, negsum);
        atomicAdd(&g_nsel, np + K);
    }
}

// ---------------------------------------------------------------------------
// Kernel 5: combine (non-selected rows each contribute exactly log C).
// ---------------------------------------------------------------------------
__global__ void k_final(float* out) {
    const int t = threadIdx.x;           // 64 threads
    int np = (t < BB) ? g_numpos[t] : 0;
    #pragma unroll
    for (int o = 16; o; o >>= 1) np += __shfl_xor_sync(FULLMASK, np, o);
    __shared__ int s_np[2];
    if ((t & 31) == 0) s_np[t >> 5] = np;
    __syncthreads();
    if (t == 0) {
        double N = (double)(s_np[0] + s_np[1]);
        double cls = g_poscls + g_negcls +
                     (double)((long long)BB * PP - (long long)g_nsel) * log((double)CC);
        out[0] = (float)(g_loc / N);
        out[1] = (float)(cls / N);
    }
}

// ---------------------------------------------------------------------------
// Launch
// ---------------------------------------------------------------------------
extern "C" void kernel_launch(void* const* d_in, const int* in_sizes, int n_in,
                              void* d_out, int out_size) {
    const float *loc = nullptr, *conf = nullptr, *tgt = nullptr, *anc = nullptr;
    for (int i = 0; i < n_in; i++) {
        long long s = in_sizes[i];
        if (s == (long long)BB * PP * 4)       loc  = (const float*)d_in[i];
        else if (s == (long long)BB * PP * CC) conf = (const float*)d_in[i];
        else if (s == (long long)BB * TT * 5)  tgt  = (const float*)d_in[i];
        else if (s == (long long)PP * 4)       anc  = (const float*)d_in[i];
    }
    float* out = (float*)d_out;

    k_init<<<(BB * TT + 255) / 256, 256>>>();

    // conf streaming + matching overlapped in one wave (740 blocks = 5/SM)
    k_fused<<<NCONF + NMATCH, 64, FUSED_SMEM>>>(conf, loc, tgt, anc);

    k_fix<<<BB, 32>>>(loc, tgt, anc);      // scatter fixup (needs g_bp, g_match)
    k_zero<<<64, 256>>>(conf);             // positive closs fixup + poscls

    k_select<<<BB, 1024>>>();

    k_final<<<1, 64>>>(out);
}

// round 13
// speedup vs baseline: 2.6247x; 2.6247x over previous
#include <cuda_runtime.h>
#include <math.h>

#define BB 64
#define PP 24564
#define CC 81
#define TT 24
#define THRESH_F 0.5f
#define FULLMASK 0xffffffffu

// fused kernel geometry: 740 blocks x 128 threads, one full wave (5 blocks/SM)
#define NBLK 740
#define CW_BUFS 2
#define CW_ROWS 32
#define CW_F4 ((CW_ROWS * CC) / 4)     // 648 float4 per tile
#define CW_TILEF (CW_ROWS * CC)        // 2592 floats
#define CONF_TILES ((BB * PP) / CW_ROWS)      // 49128
#define NCWARPS (NBLK * 2)             // 1480 conf warps (warps 0,1 of each block)
#define NMWARPS (NBLK * 2)             // 1480 match warps (warps 2,3)
#define MCH_PER_B 768                  // 32-prior chunks per batch
#define MCHUNKS (MCH_PER_B * BB)       // 49152
// smem: 2 conf warps * 2 bufs * 2592 floats + 2 match warps * 256 floats
#define SMEM_CONF_F (2 * CW_BUFS * CW_TILEF)      // 10368 floats
#define FUSED_SMEM ((SMEM_CONF_F + 2 * 256) * 4)  // 43520 B

// ---------------------------------------------------------------------------
// Scratch (device globals — no allocation allowed)
// ---------------------------------------------------------------------------
__device__ unsigned long long g_bp[BB * TT];        // packed (iou_bits<<32)|~p
__device__ unsigned char g_match[(size_t)BB * PP];  // 0xFF = bestov<=0.5, else bt
__device__ float g_closs[(size_t)BB * PP];          // lse - c0 raw; positives zeroed later
__device__ unsigned int g_plist[(size_t)BB * PP];   // packed (row<<8)|lbl
__device__ int g_pcount;
__device__ double g_loc, g_poscls, g_negcls;
__device__ int g_numpos[BB];
__device__ int g_nsel;

__device__ __forceinline__ void cp_async16(unsigned int smem_dst, const void* gsrc) {
    asm volatile("cp.async.cg.shared.global [%0], [%1], 16;"
                 :: "r"(smem_dst), "l"(gsrc));
}

// ---------------------------------------------------------------------------
// Kernel 0: zero-init scratch
// ---------------------------------------------------------------------------
__global__ void k_init() {
    int i = blockIdx.x * blockDim.x + threadIdx.x;
    if (i < BB * TT) g_bp[i] = 0ULL;
    if (i < BB) g_numpos[i] = 0;
    if (i == 0) { g_loc = 0.0; g_poscls = 0.0; g_negcls = 0.0; g_nsel = 0; g_pcount = 0; }
}

// ---------------------------------------------------------------------------
// Kernel 1 (FUSED, balanced): every block = 2 conf warps + 2 match warps.
// conf (warps 0,1): R10's cp.async double-buffered stream, 1480 warps,
//   memory-bound at the ~4 TB/s wall, issue slots mostly idle.
// match (warps 2,3): 1480 warps x 32 lanes -> ~33 priors/lane, compute work
//   hides in conf's idle issue slots. conf does NOT depend on match: it
//   writes closs_raw = lse - c0 for ALL rows; positives recorded in g_plist
//   and fixed by k_zero afterwards.
// ---------------------------------------------------------------------------
__global__ void __launch_bounds__(128) k_fused(const float* __restrict__ conf_pred,
                                               const float* __restrict__ loc_pred,
                                               const float* __restrict__ targets,
                                               const float* __restrict__ anchors) {
    extern __shared__ float smem[];
    const int lane = threadIdx.x & 31;
    const int w = threadIdx.x >> 5;

    if (w < 2) {
        // ================= CONF PATH (R10 design, best measured) =============
        const int gw = blockIdx.x * 2 + w;               // 0..1479
        float* wbase = smem + w * (CW_BUFS * CW_TILEF);
        unsigned int sb0 = (unsigned int)__cvta_generic_to_shared(wbase);

        int tile = gw;
        {
            const float4* src = (const float4*)(conf_pred + (size_t)tile * CW_TILEF);
            #pragma unroll
            for (int i = lane; i < CW_F4; i += 32)
                cp_async16(sb0 + i * 16, src + i);
            asm volatile("cp.async.commit_group;");
        }
        int buf = 0;
        for (; tile < CONF_TILES; tile += NCWARPS) {
            const int nt = tile + NCWARPS;
            if (nt < CONF_TILES) {
                const float4* src = (const float4*)(conf_pred + (size_t)nt * CW_TILEF);
                unsigned int dst = sb0 + (buf ^ 1) * (CW_TILEF * 4);
                #pragma unroll
                for (int i = lane; i < CW_F4; i += 32)
                    cp_async16(dst + i * 16, src + i);
            }
            asm volatile("cp.async.commit_group;");
            asm volatile("cp.async.wait_group 1;");
            __syncwarp();

            const float* rp = wbase + buf * CW_TILEF + lane * CC;
            float a0 = 0.f, a1 = 0.f, a2 = 0.f;
            #pragma unroll 9
            for (int e = 0; e < CC; e += 3) {
                a0 += __expf(rp[e]);
                a1 += __expf(rp[e + 1]);
                a2 += __expf(rp[e + 2]);
            }
            const float lse = __logf((a0 + a1) + a2);
            g_closs[(size_t)tile * CW_ROWS + lane] = lse - rp[0];   // raw, ALL rows

            buf ^= 1;
            __syncwarp();
        }
    } else {
        // ================= MATCH PATH (1480 warps, ~33 priors/lane) ==========
        const int gw2 = blockIdx.x * 2 + (w - 2);        // 0..1479
        float* tc = smem + SMEM_CONF_F + (w - 2) * 256;  // warp-private truth cache
        float* t_box = tc;            // [24][4] xyxy
        float* t_ta  = tc + 96;       // [24]
        float* t_cwh = tc + 120;      // [24][4]
        float* t_lbl = tc + 216;      // [24]

        const int c0 = (int)(((long long)gw2 * MCHUNKS) / NMWARPS);
        const int c1 = (int)(((long long)(gw2 + 1) * MCHUNKS) / NMWARPS);

        unsigned int cur[TT];         // warp-uniform running max (iou bits)
        int bcur = -1;

        for (int c = c0; c < c1; c++) {
            const int b = c / MCH_PER_B;
            const int p = (c - b * MCH_PER_B) * 32 + lane;
            if (b != bcur) {
                __syncwarp();
                if (lane < TT) {
                    const float* tr = targets + ((size_t)b * TT + lane) * 5;
                    float x0 = tr[0], y0 = tr[1], x1 = tr[2], y1 = tr[3];
                    t_box[lane * 4 + 0] = x0; t_box[lane * 4 + 1] = y0;
                    t_box[lane * 4 + 2] = x1; t_box[lane * 4 + 3] = y1;
                    t_ta[lane] = (x1 - x0) * (y1 - y0);
                    t_cwh[lane * 4 + 0] = (x0 + x1) * 0.5f;
                    t_cwh[lane * 4 + 1] = (y0 + y1) * 0.5f;
                    t_cwh[lane * 4 + 2] = x1 - x0;
                    t_cwh[lane * 4 + 3] = y1 - y0;
                    t_lbl[lane] = tr[4];
                }
                __syncwarp();
                #pragma unroll
                for (int t = 0; t < TT; t++) cur[t] = 0u;
                bcur = b;
            }

            const bool valid = (p < PP);
            float4 a = make_float4(0.f, 0.f, 1.f, 1.f);
            if (valid) a = ((const float4*)anchors)[p];
            const float ax0 = a.x - a.z * 0.5f, ay0 = a.y - a.w * 0.5f;
            const float ax1 = a.x + a.z * 0.5f, ay1 = a.y + a.w * 0.5f;
            const float aarea = (ax1 - ax0) * (ay1 - ay0);

            float best = -1.0f; int bt = 0;
            #pragma unroll
            for (int t = 0; t < TT; t++) {
                float lx = fmaxf(t_box[t * 4 + 0], ax0), ly = fmaxf(t_box[t * 4 + 1], ay0);
                float rx = fminf(t_box[t * 4 + 2], ax1), ry = fminf(t_box[t * 4 + 3], ay1);
                float ww = fmaxf(rx - lx, 0.f), hh = fmaxf(ry - ly, 0.f);
                float inter = ww * hh;
                float iou = __fdividef(inter, t_ta[t] + aarea - inter);
                if (iou > best) { best = iou; bt = t; }   // strict >: first index
                unsigned int ib = valid ? __float_as_uint(iou) : 0u;
                if (__any_sync(FULLMASK, ib > cur[t])) {
                    unsigned long long pk = valid
                        ? (((unsigned long long)ib << 32)
                           | (unsigned long long)(unsigned int)(~p))
                        : 0ULL;
                    #pragma unroll
                    for (int o = 16; o; o >>= 1) {
                        unsigned long long q = __shfl_xor_sync(FULLMASK, pk, o);
                        if (q > pk) pk = q;
                    }
                    cur[t] = (unsigned int)(pk >> 32);
                    if (lane == 0) atomicMax(&g_bp[b * TT + t], pk);
                }
            }

            const bool pos = valid && (best > THRESH_F);
            const unsigned int pm = __ballot_sync(FULLMASK, pos);
            const unsigned int row = (unsigned int)(b * PP + p);
            float lt = 0.f; int lbl = 0;
            if (pos) {
                lbl = (int)t_lbl[bt];
                float4 lp = ((const float4*)loc_pred)[row];
                float e0 = (t_cwh[bt * 4 + 0] - a.x) / a.z;
                float e1 = (t_cwh[bt * 4 + 1] - a.y) / a.w;
                float e2 = __logf(t_cwh[bt * 4 + 2]) - __logf(a.z);
                float e3 = __logf(t_cwh[bt * 4 + 3]) - __logf(a.w);
                float d, ad;
                d = lp.x - e0; ad = fabsf(d); lt += (ad < 1.f) ? 0.5f * d * d : ad - 0.5f;
                d = lp.y - e1; ad = fabsf(d); lt += (ad < 1.f) ? 0.5f * d * d : ad - 0.5f;
                d = lp.z - e2; ad = fabsf(d); lt += (ad < 1.f) ? 0.5f * d * d : ad - 0.5f;
                d = lp.w - e3; ad = fabsf(d); lt += (ad < 1.f) ? 0.5f * d * d : ad - 0.5f;
            }
            if (pm) {   // warp-aggregated positive bookkeeping
                const int n = __popc(pm);
                const int leader = __ffs(pm) - 1;
                unsigned int base = 0;
                if (lane == leader) base = (unsigned int)atomicAdd(&g_pcount, n);
                base = __shfl_sync(FULLMASK, base, leader);
                if (pos) {
                    int off = __popc(pm & ((1u << lane) - 1u));
                    g_plist[base + off] = (row << 8) | (unsigned int)lbl;
                }
                double dlt = (double)lt;
                #pragma unroll
                for (int o = 16; o; o >>= 1) dlt += __shfl_xor_sync(FULLMASK, dlt, o);
                if (lane == leader) {
                    atomicAdd(&g_loc, dlt);
                    atomicAdd(&g_numpos[b], n);
                }
            }
            if (valid) g_match[row] = pos ? (unsigned char)bt : (unsigned char)0xFF;
        }
    }
}

// ---------------------------------------------------------------------------
// Kernel 2: scatter fixup — row p = best_prior[b][t] becomes positive with
// truth t (last t wins among duplicates) iff its best overlap <= 0.5.
// ---------------------------------------------------------------------------
__global__ void k_fix(const float* __restrict__ loc_pred,
                      const float* __restrict__ targets,
                      const float* __restrict__ anchors) {
    const int b = blockIdx.x;
    const int t = threadIdx.x;
    if (t >= TT) return;
    unsigned long long pk = g_bp[b * TT + t];
    const int p = (int)(~(unsigned int)(pk & 0xFFFFFFFFull));
    unsigned int peers = __match_any_sync(0x00FFFFFFu, p);
    if (t != 31 - __clz(peers)) return;          // last t wins
    const unsigned int row = (unsigned int)(b * PP + p);
    if (g_match[row] != 0xFF) return;            // bt-match already positive

    const float* tr = targets + ((size_t)b * TT + t) * 5;
    float x0 = tr[0], y0 = tr[1], x1 = tr[2], y1 = tr[3];
    int lbl = (int)tr[4];
    int idx = atomicAdd(&g_pcount, 1);
    g_plist[idx] = (row << 8) | (unsigned int)lbl;

    float4 a = ((const float4*)anchors)[p];
    float4 lp = ((const float4*)loc_pred)[row];
    float e0 = ((x0 + x1) * 0.5f - a.x) / a.z;
    float e1 = ((y0 + y1) * 0.5f - a.y) / a.w;
    float e2 = __logf(x1 - x0) - __logf(a.z);
    float e3 = __logf(y1 - y0) - __logf(a.w);
    float d, ad, lt = 0.f;
    d = lp.x - e0; ad = fabsf(d); lt += (ad < 1.f) ? 0.5f * d * d : ad - 0.5f;
    d = lp.y - e1; ad = fabsf(d); lt += (ad < 1.f) ? 0.5f * d * d : ad - 0.5f;
    d = lp.z - e2; ad = fabsf(d); lt += (ad < 1.f) ? 0.5f * d * d : ad - 0.5f;
    d = lp.w - e3; ad = fabsf(d); lt += (ad < 1.f) ? 0.5f * d * d : ad - 0.5f;
    atomicAdd(&g_loc, (double)lt);
    atomicAdd(&g_numpos[b], 1);
}

// ---------------------------------------------------------------------------
// Kernel 3: positive fixup (high-parallelism). For each (row,lbl) in g_plist:
//   poscls += closs_raw[row] + conf[row][0] - conf[row][lbl]   (= lse - conf[lbl])
//   closs[row] = 0
// ---------------------------------------------------------------------------
__global__ void k_zero(const float* __restrict__ conf_pred) {
    const int n = g_pcount;
    const int lane = threadIdx.x & 31;
    double acc = 0.0;
    for (int i = blockIdx.x * blockDim.x + threadIdx.x; i < n;
         i += gridDim.x * blockDim.x) {
        unsigned int e = g_plist[i];
        size_t row = (size_t)(e >> 8);
        int lbl = (int)(e & 255u);
        const float* cp = conf_pred + row * CC;
        acc += (double)(g_closs[row] + __ldg(cp) - __ldg(cp + lbl));
        g_closs[row] = 0.f;
    }
    #pragma unroll
    for (int o = 16; o; o >>= 1) acc += __shfl_xor_sync(FULLMASK, acc, o);
    if (lane == 0 && acc != 0.0) atomicAdd(&g_poscls, acc);
}

// ---------------------------------------------------------------------------
// Kernel 4: per-batch exact K-th-largest; register-cached values, warp-
// aggregated histogram atomics (closs clusters into few bins).
// ---------------------------------------------------------------------------
__global__ void __launch_bounds__(1024) k_select() {
    __shared__ int hist[256];
    __shared__ unsigned int s_sel;
    __shared__ int s_r;
    __shared__ double s_sum;
    __shared__ int s_cnt;

    const int b = blockIdx.x;
    const int tid = threadIdx.x;
    const int lane = tid & 31;
    const int np = g_numpos[b];
    long long Kl = 3LL * np;
    if (Kl > PP - 1) Kl = PP - 1;
    const int K = (int)Kl;
    if (K <= 0) {
        if (tid == 0) atomicAdd(&g_nsel, np);
        return;
    }
    const float* cl = g_closs + (size_t)b * PP;

    // Padding 0u (=0.0f) lands in bin 0; selection never descends there
    // (K-th largest closs > 0).
    unsigned int v[24];
    #pragma unroll
    for (int i = 0; i < 24; i++) {
        int idx = tid + i * 1024;
        v[i] = (idx < PP) ? __float_as_uint(cl[idx]) : 0u;
    }

    unsigned int prefix = 0, pmask = 0;
    int r = K;
    #pragma unroll
    for (int shift = 24; shift >= 0; shift -= 8) {
        if (tid < 256) hist[tid] = 0;
        __syncthreads();
        #pragma unroll
        for (int i = 0; i < 24; i++) {
            unsigned int u = v[i];
            bool act = ((u & pmask) == prefix);
            unsigned int bal = __ballot_sync(FULLMASK, act);
            if (act) {
                unsigned int bin = (u >> shift) & 255u;
                unsigned int peers = __match_any_sync(bal, bin);
                if (lane == __ffs(peers) - 1)
                    atomicAdd(&hist[bin], __popc(peers));
            }
        }
        __syncthreads();
        if (tid == 0) {
            int cum = 0; unsigned int sel = 0;
            for (int bin = 255; bin >= 0; bin--) {
                int nc = cum + hist[bin];
                if (nc >= r) { sel = (unsigned int)bin; break; }
                cum = nc;
            }
            s_sel = sel; s_r = r - cum;
        }
        __syncthreads();
        prefix |= s_sel << shift;
        pmask |= 0xFFu << shift;
        r = s_r;
    }
    const float theta = __uint_as_float(prefix);   // exact K-th largest

    if (tid == 0) { s_sum = 0.0; s_cnt = 0; }
    __syncthreads();
    double sum = 0.0; int cnt = 0;
    #pragma unroll
    for (int i = 0; i < 24; i++) {
        float f = __uint_as_float(v[i]);
        if (f > theta) { sum += (double)f; cnt++; }
    }
    #pragma unroll
    for (int o = 16; o; o >>= 1) {
        sum += __shfl_xor_sync(FULLMASK, sum, o);
        cnt += __shfl_xor_sync(FULLMASK, cnt, o);
    }
    if (lane == 0) { atomicAdd(&s_sum, sum); atomicAdd(&s_cnt, cnt); }
    __syncthreads();
    if (tid == 0) {
        double negsum = s_sum + (double)(K - s_cnt) * (double)theta;
        atomicAdd(&g_negcls, negsum);
        atomicAdd(&g_nsel, np + K);
    }
}

// ---------------------------------------------------------------------------
// Kernel 5: combine (non-selected rows each contribute exactly log C).
// ---------------------------------------------------------------------------
__global__ void k_final(float* out) {
    const int t = threadIdx.x;           // 64 threads
    int np = (t < BB) ? g_numpos[t] : 0;
    #pragma unroll
    for (int o = 16; o; o >>= 1) np += __shfl_xor_sync(FULLMASK, np, o);
    __shared__ int s_np[2];
    if ((t & 31) == 0) s_np[t >> 5] = np;
    __syncthreads();
    if (t == 0) {
        double N = (double)(s_np[0] + s_np[1]);
        double cls = g_poscls + g_negcls +
                     (double)((long long)BB * PP - (long long)g_nsel) * log((double)CC);
        out[0] = (float)(g_loc / N);
        out[1] = (float)(cls / N);
    }
}

// ---------------------------------------------------------------------------
// Launch
// ---------------------------------------------------------------------------
extern "C" void kernel_launch(void* const* d_in, const int* in_sizes, int n_in,
                              void* d_out, int out_size) {
    const float *loc = nullptr, *conf = nullptr, *tgt = nullptr, *anc = nullptr;
    for (int i = 0; i < n_in; i++) {
        long long s = in_sizes[i];
        if (s == (long long)BB * PP * 4)       loc  = (const float*)d_in[i];
        else if (s == (long long)BB * PP * CC) conf = (const float*)d_in[i];
        else if (s == (long long)BB * TT * 5)  tgt  = (const float*)d_in[i];
        else if (s == (long long)PP * 4)       anc  = (const float*)d_in[i];
    }
    float* out = (float*)d_out;

    k_init<<<(BB * TT + 255) / 256, 256>>>();

    // conf streaming + matching overlapped, balanced within every block
    k_fused<<<NBLK, 128, FUSED_SMEM>>>(conf, loc, tgt, anc);

    k_fix<<<BB, 32>>>(loc, tgt, anc);      // scatter fixup (needs g_bp, g_match)
    k_zero<<<592, 128>>>(conf);            // positive closs fixup + poscls

    k_select<<<BB, 1024>>>();

    k_final<<<1, 64>>>(out);
}